// round 9
// baseline (speedup 1.0000x reference)
#include <cuda_runtime.h>
#include <cuda_bf16.h>
#include <cstdint>
#include <math.h>

// simpleLSTM B=64 T=1024 I=512 H=1024 — v9: v8 (16-warp HMMA bf16-2split,
// persistent, A global->register) + CTA-skewed chunk order (L2 decorrelation),
// 4-replica grid barrier, fast-math gates.

namespace {
constexpr int kB=64, kT=1024, kI=512, kH=1024;
constexpr int kNCTA=128, kNTHR=512;
constexpr int BLOB=8192;               // per-chunk A fragment blob (hi+lo)
constexpr int WHI=0;                   // 24 weight tiles x 4096B
constexpr int WLO=98304;
constexpr int ACC0=196608;             // [4 k-groups][64][34] f32
constexpr int ACCSTR=34;
constexpr int ACCSZ=64*ACCSTR*4;       // 8704
constexpr int SMEMB=ACC0+4*ACCSZ;      // 231424
}

__device__ unsigned char g_xt[(size_t)kT*16*BLOB];   // x fragment blobs
__device__ unsigned char g_ht[(size_t)2*32*BLOB];    // h blobs: 2 par x 32
__device__ int g_arr4[kT*4];                         // 4-replica barrier

__device__ __forceinline__ uint32_t smem_u32_of(const void* p) {
    uint32_t a;
    asm("{ .reg .u64 t0; cvta.to.shared.u64 t0, %1; cvt.u32.u64 %0, t0; }"
        : "=r"(a) : "l"(p));
    return a;
}
__device__ __forceinline__ uint32_t swz128(uint32_t o) { return o ^ ((o >> 3) & 0x70); }
__device__ __forceinline__ float sigf(float x) {
    return __fdividef(1.0f, 1.0f + __expf(-x));
}
__device__ __forceinline__ float tanh_fast(float x) {
    float xc = fminf(fmaxf(x, -15.0f), 15.0f);
    float t = __expf(2.0f * xc);
    return __fdividef(t - 1.0f, t + 1.0f);
}
__device__ __forceinline__ void spin_on(const int* p, uint32_t n) {
    uint32_t v;
    do {
        asm volatile("ld.acquire.gpu.global.u32 %0, [%1];" : "=r"(v) : "l"(p) : "memory");
    } while (v < n);
}

#define LDSM4(R, A) \
    asm volatile("ldmatrix.sync.aligned.m8n8.x4.shared.b16 {%0,%1,%2,%3}, [%4];" \
        : "=r"((R)[0]), "=r"((R)[1]), "=r"((R)[2]), "=r"((R)[3]) : "r"(A))

#define MMA16816(D, A, B0, B1) \
    asm volatile("mma.sync.aligned.m16n8k16.row.col.f32.bf16.bf16.f32 " \
        "{%0,%1,%2,%3}, {%4,%5,%6,%7}, {%8,%9}, {%0,%1,%2,%3};" \
        : "+f"((D)[0]), "+f"((D)[1]), "+f"((D)[2]), "+f"((D)[3]) \
        : "r"((A)[0]), "r"((A)[1]), "r"((A)[2]), "r"((A)[3]), "r"(B0), "r"(B1))

__global__ void lstm9_init() {
    int i = blockIdx.x * blockDim.x + threadIdx.x;
    if (i < kT * 4) g_arr4[i] = 0;
    if (i < (int)(sizeof(g_ht) / 16))
        ((uint4*)g_ht)[i] = make_uint4(0u, 0u, 0u, 0u);
}

// x fragment blobs: block = t*16 + c. Layout per (s,ks):
// hi: s*2048 + ks*512 + lane*16 + r*4 ; lo at +1024.
__global__ void __launch_bounds__(128) lstm9_xsplit(const float* __restrict__ x) {
    __shared__ float xt[64 * 32];
    const int bx = blockIdx.x, t = bx >> 4, c = bx & 15, tid = threadIdx.x;
    #pragma unroll
    for (int v = 0; v < 4; ++v) {
        int idx = tid + v * 128;
        int b = idx >> 3, ko = (idx & 7) * 4;
        float4 f = *(const float4*)(x + ((size_t)b * kT + t) * kI + c * 32 + ko);
        *(float4*)(xt + b * 32 + ko) = f;
    }
    __syncthreads();
    const int s = tid >> 5, ks = (tid >> 4) & 1, l2 = tid & 15;
    unsigned char* base = g_xt + (size_t)bx * BLOB + s * 2048 + ks * 512;
    #pragma unroll
    for (int dl = 0; dl < 2; ++dl) {
        int l = l2 * 2 + dl;
        uint32_t hi[4], lo[4];
        #pragma unroll
        for (int r = 0; r < 4; ++r) {
            int row = s * 16 + (l >> 2) + 8 * (r & 1);
            int col = ks * 16 + 8 * (r >> 1) + (l & 3) * 2;
            float f0 = xt[row * 32 + col], f1 = xt[row * 32 + col + 1];
            __nv_bfloat16 h0 = __float2bfloat16(f0);
            __nv_bfloat16 h1 = __float2bfloat16(f1);
            __nv_bfloat162 hp; hp.x = h0; hp.y = h1;
            __nv_bfloat162 lp = __floats2bfloat162_rn(
                f0 - __bfloat162float(h0), f1 - __bfloat162float(h1));
            hi[r] = *(uint32_t*)&hp;
            lo[r] = *(uint32_t*)&lp;
        }
        *(uint4*)(base + l * 16)        = make_uint4(hi[0], hi[1], hi[2], hi[3]);
        *(uint4*)(base + 1024 + l * 16) = make_uint4(lo[0], lo[1], lo[2], lo[3]);
    }
}

__device__ __forceinline__ const unsigned char* ablob9(int t, int c, int s) {
    if (c < 16) return g_xt + (((size_t)(t * 16 + c)) << 13) + s * 2048;
    return g_ht + (((size_t)((t & 1) * 32 + (c - 16))) << 13) + s * 2048;
}
__device__ __forceinline__ void lda(uint4* a, const unsigned char* p, int lane) {
    a[0] = __ldcg((const uint4*)(p + lane * 16));
    a[1] = __ldcg((const uint4*)(p + 512 + lane * 16));
    a[2] = __ldcg((const uint4*)(p + 1024 + lane * 16));
    a[3] = __ldcg((const uint4*)(p + 1536 + lane * 16));
}
// CTA-skewed chunk order: x iters (i<4) rotated by px, h iters by ph.
__device__ __forceinline__ int cidx(int i, int g, int px, int ph) {
    return (i < 4) ? (4 * ((i + px) & 3) + g)
                   : (16 + 4 * (((i - 4) + ph) & 7) + g);
}

__global__ void __launch_bounds__(kNTHR, 1) lstm9_kernel(
    const float* __restrict__ Wf, const float* __restrict__ bf,
    const float* __restrict__ Wi, const float* __restrict__ bi,
    const float* __restrict__ Wo, const float* __restrict__ bo,
    const float* __restrict__ Wc, const float* __restrict__ bc,
    float* __restrict__ out)
{
    extern __shared__ unsigned char smem[];
    const uint32_t sb = smem_u32_of(smem);
    const int tid = threadIdx.x, lane = tid & 31, w = tid >> 5;
    const int g = w >> 2, s = w & 3;      // k-group (4), m-slice (4)
    const int cta = blockIdx.x, j0 = cta * 8;
    const int px = cta & 3, ph = cta & 7;

    // ---- stage weights bf16 hi/lo SW128 K=64 tiles (once) ----
    {
        const float* const Wp[4] = {Wf, Wi, Wo, Wc};
        for (int r = 0; r < 32; ++r) {
            const float* src = Wp[r & 3] + (size_t)(j0 + (r >> 2)) * 1536;
            for (int kp = tid; kp < 768; kp += kNTHR) {
                int k = kp * 2;
                float f0 = __ldg(src + k), f1 = __ldg(src + k + 1);
                __nv_bfloat16 h0 = __float2bfloat16(f0);
                __nv_bfloat16 h1 = __float2bfloat16(f1);
                __nv_bfloat162 hp; hp.x = h0; hp.y = h1;
                __nv_bfloat162 lp = __floats2bfloat162_rn(
                    f0 - __bfloat162float(h0), f1 - __bfloat162float(h1));
                uint32_t off = swz128((uint32_t)((k >> 6) * 4096 + (r << 7) + ((k & 63) << 1)));
                *(uint32_t*)(smem + WHI + off) = *(uint32_t*)&hp;
                *(uint32_t*)(smem + WLO + off) = *(uint32_t*)&lp;
            }
        }
    }

    // B ldmatrix addressing
    const int rowB = ((lane >> 4) << 3) + (lane & 7);
    const uint32_t bRow = (uint32_t)rowB * 128;
    const int bXor = rowB & 7, bCB = (lane >> 3) & 1;

    // acc staging
    const int m0 = s * 16;
    const int mA = m0 + (lane >> 2), cA = (lane & 3) * 2;
    float* abuf = (float*)(smem + ACC0 + g * ACCSZ);

    // epilogue ownership: thread -> (eb, unit jl)
    const int eb = tid & 63, jl = tid >> 6;
    float bb[4];
    {
        const float* const Bp[4] = {bf, bi, bo, bc};
        #pragma unroll
        for (int q = 0; q < 4; ++q) bb[q] = __ldg(Bp[q] + j0 + jl);
    }
    // h fragment write address pieces
    const int colh = (j0 & 31) + jl;
    const int s2 = eb >> 4, ri16 = eb & 15;
    const int lane2 = (ri16 & 7) * 4 + ((colh & 7) >> 1);
    const int r2 = (ri16 >> 3) + 2 * ((colh & 15) >> 3);
    const int ks2 = (colh >> 4) & 1;
    const size_t hoff = (size_t)s2 * 2048 + ks2 * 512 + lane2 * 16 + r2 * 4 + (colh & 1) * 2;
    const size_t hcsel = (size_t)(j0 >> 5) << 13;

    float cs = 0.0f;
    __syncthreads();

    uint4 ap[3][4];
    lda(ap[0], ablob9(0, cidx(0, g, px, ph), s), lane);
    lda(ap[1], ablob9(0, cidx(1, g, px, ph), s), lane);

    for (int t = 0; t < kT; ++t) {
        float acc[4][4];
        #pragma unroll
        for (int nt = 0; nt < 4; ++nt)
            #pragma unroll
            for (int e = 0; e < 4; ++e) acc[nt][e] = 0.0f;

        #pragma unroll 3
        for (int i = 0; i < 12; ++i) {
            // per-warp JIT grid barrier; first h prefetch (i+2==4) follows it
            if (t > 0 && i == 2)
                spin_on(g_arr4 + (t - 1) * 4 + px, kNCTA);
            if (i < 10)
                lda(ap[(i + 2) % 3], ablob9(t, cidx(i + 2, g, px, ph), s), lane);

            const int c = cidx(i, g, px, ph);
            const uint32_t bhB = sb + WHI + (uint32_t)(c >> 1) * 4096;
            const int ksg0 = (c & 1) * 2;
            #pragma unroll
            for (int ks = 0; ks < 2; ++ks) {
                uint32_t bh0[4], bh1[4], bl0[4], bl1[4];
                uint32_t cb = (uint32_t)(((2 * (ksg0 + ks) + bCB) ^ bXor) << 4);
                LDSM4(bh0, bhB + bRow + cb);
                LDSM4(bh1, bhB + bRow + cb + 2048);
                LDSM4(bl0, bhB + (WLO - WHI) + bRow + cb);
                LDSM4(bl1, bhB + (WLO - WHI) + bRow + cb + 2048);
                const uint32_t* ah = (const uint32_t*)&ap[i % 3][ks];
                const uint32_t* al = (const uint32_t*)&ap[i % 3][2 + ks];
                MMA16816(acc[0], ah, bh0[0], bh0[1]);
                MMA16816(acc[1], ah, bh0[2], bh0[3]);
                MMA16816(acc[2], ah, bh1[0], bh1[1]);
                MMA16816(acc[3], ah, bh1[2], bh1[3]);
                MMA16816(acc[0], ah, bl0[0], bl0[1]);
                MMA16816(acc[1], ah, bl0[2], bl0[3]);
                MMA16816(acc[2], ah, bl1[0], bl1[1]);
                MMA16816(acc[3], ah, bl1[2], bl1[3]);
                MMA16816(acc[0], al, bh0[0], bh0[1]);
                MMA16816(acc[1], al, bh0[2], bh0[3]);
                MMA16816(acc[2], al, bh1[0], bh1[1]);
                MMA16816(acc[3], al, bh1[2], bh1[3]);
            }
        }

        // prefetch next step's first two (x) chunks during epilogue
        if (t + 1 < kT) {
            lda(ap[0], ablob9(t + 1, cidx(0, g, px, ph), s), lane);
            lda(ap[1], ablob9(t + 1, cidx(1, g, px, ph), s), lane);
        }

        // ---- stage partial D into this k-group's buffer ----
        #pragma unroll
        for (int nt = 0; nt < 4; ++nt) {
            abuf[mA * ACCSTR + nt * 8 + cA]           = acc[nt][0];
            abuf[mA * ACCSTR + nt * 8 + cA + 1]       = acc[nt][1];
            abuf[(mA + 8) * ACCSTR + nt * 8 + cA]     = acc[nt][2];
            abuf[(mA + 8) * ACCSTR + nt * 8 + cA + 1] = acc[nt][3];
        }
        __syncthreads();

        // ---- epilogue: each thread owns (eb, jl) ----
        {
            const float* a0 = (const float*)(smem + ACC0);
            float sum[4];
            #pragma unroll
            for (int q = 0; q < 4; ++q) sum[q] = bb[q];
            #pragma unroll
            for (int bq = 0; bq < 4; ++bq) {
                const float* ab = a0 + bq * (ACCSZ / 4) + eb * ACCSTR + jl * 4;
                #pragma unroll
                for (int q = 0; q < 4; ++q) sum[q] += ab[q];
            }
            float f = sigf(sum[0]), ii = sigf(sum[1]);
            float o = sigf(sum[2]), gg = tanh_fast(sum[3]);
            float cn = f * cs + ii * gg;
            cs = cn;
            float hv = o * tanh_fast(cn);

            if (t < kT - 1) {
                __nv_bfloat16 hb = __float2bfloat16(hv);
                unsigned char* dst = g_ht + ((size_t)(((t & 1) ^ 1) * 32) << 13)
                                   + hcsel + hoff;
                *(__nv_bfloat16*)dst          = hb;
                *(__nv_bfloat16*)(dst + 1024) =
                    __float2bfloat16(hv - __bfloat162float(hb));
                __threadfence();
            } else {
                out[eb * kH + j0 + jl]           = hv;
                out[kB * kH + eb * kH + j0 + jl] = cs;
            }
        }
        __syncthreads();
        // post to all 4 replicas (lanes 0..3 of warp 0), release semantics
        if (t < kT - 1 && tid < 4) {
            asm volatile("red.release.gpu.global.add.u32 [%0], %1;"
                         :: "l"(g_arr4 + t * 4 + tid), "r"(1u) : "memory");
        }
    }
}

extern "C" void kernel_launch(void* const* d_in, const int* in_sizes, int n_in,
                              void* d_out, int out_size)
{
    (void)in_sizes; (void)n_in; (void)out_size;
    const float* x  = (const float*)d_in[0];
    const float* Wf = (const float*)d_in[1];
    const float* bf = (const float*)d_in[2];
    const float* Wi = (const float*)d_in[3];
    const float* bi = (const float*)d_in[4];
    const float* Wo = (const float*)d_in[5];
    const float* bo = (const float*)d_in[6];
    const float* Wc = (const float*)d_in[7];
    const float* bc = (const float*)d_in[8];
    float* out = (float*)d_out;

    cudaFuncSetAttribute(lstm9_kernel,
                         cudaFuncAttributeMaxDynamicSharedMemorySize, SMEMB);
    lstm9_init<<<256, 256>>>();
    lstm9_xsplit<<<kT * 16, 128>>>(x);
    lstm9_kernel<<<kNCTA, kNTHR, SMEMB>>>(Wf, bf, Wi, bi, Wo, bo, Wc, bc, out);
}